// round 4
// baseline (speedup 1.0000x reference)
#include <cuda_runtime.h>
#include <cstdint>

#define S_STEPS 19648   // B*N = 64*307 sequential LSTM steps
#define NCH 12          // T_IN: independent LSTM chains
#define HID 128
#define CLS 8           // CTAs per chain (cluster size)
#define NROWS_TOTAL (S_STEPS * NCH)

// h history for deferred output projection: 19648*12*128 floats = ~115 MB
__device__ float g_hhist[(size_t)S_STEPS * NCH * HID];

// ---------------- PTX helpers ----------------
__device__ __forceinline__ uint32_t smem_u32(const void* p) {
    uint32_t a;
    asm("{ .reg .u64 t; cvta.to.shared.u64 t, %1; cvt.u32.u64 %0, t; }"
        : "=r"(a) : "l"(p));
    return a;
}
__device__ __forceinline__ uint32_t my_cluster_rank() {
    uint32_t r; asm("mov.u32 %0, %%cluster_ctarank;" : "=r"(r)); return r;
}
__device__ __forceinline__ uint32_t mapa_u32(uint32_t laddr, uint32_t rk) {
    uint32_t r;
    asm("mapa.shared::cluster.u32 %0, %1, %2;" : "=r"(r) : "r"(laddr), "r"(rk));
    return r;
}
__device__ __forceinline__ void st_async_f32(uint32_t raddr, float v, uint32_t rmbar) {
    asm volatile(
        "st.async.shared::cluster.mbarrier::complete_tx::bytes.b32 [%0], %1, [%2];"
        :: "r"(raddr), "r"(__float_as_uint(v)), "r"(rmbar) : "memory");
}
#define MBAR_INIT(a, n) \
    asm volatile("mbarrier.init.shared.b64 [%0], %1;" :: "r"(a), "r"((uint32_t)(n)) : "memory")
#define MBAR_EXPECT_TX(a, n) \
    asm volatile("mbarrier.arrive.expect_tx.shared.b64 _, [%0], %1;" :: "r"(a), "r"((uint32_t)(n)) : "memory")
#define MBAR_WAIT(a, par) do {                                              \
    asm volatile(                                                           \
        "{\n\t.reg .pred P1;\n\t"                                           \
        "WL_%=:\n\t"                                                        \
        "mbarrier.try_wait.parity.acquire.cta.shared::cta.b64 P1, [%0], %1, 0x989680;\n\t" \
        "@P1 bra.uni WD_%=;\n\t"                                            \
        "bra.uni WL_%=;\n\t"                                                \
        "WD_%=:\n\t}"                                                       \
        :: "r"(a), "r"((uint32_t)(par)) : "memory");                        \
} while (0)

__device__ __forceinline__ unsigned long long fma2(unsigned long long a,
                                                   unsigned long long b,
                                                   unsigned long long c) {
    unsigned long long d;
    asm("fma.rn.f32x2 %0, %1, %2, %3;" : "=l"(d) : "l"(a), "l"(b), "l"(c));
    return d;
}
__device__ __forceinline__ float unpack_sum(unsigned long long a) {
    uint32_t lo, hi;
    asm("mov.b64 {%0, %1}, %2;" : "=r"(lo), "=r"(hi) : "l"(a));
    return __uint_as_float(lo) + __uint_as_float(hi);
}
__device__ __forceinline__ float tanh_fast(float x) {
    float y; asm("tanh.approx.f32 %0, %1;" : "=f"(y) : "f"(x)); return y;
}
__device__ __forceinline__ float sigmoid_fast(float x) {
    return fmaf(0.5f, tanh_fast(0.5f * x), 0.5f);
}
#define CLUSTER_SYNC() do { \
    asm volatile("barrier.cluster.arrive.aligned;" ::: "memory"); \
    asm volatile("barrier.cluster.wait.aligned;"   ::: "memory"); } while (0)

// ---------------- LSTM kernel ----------------
// 96 CTAs = 12 chains x 8-CTA clusters. CTA rank r owns hidden units
// [16r, 16r+16) = 64 gate rows. Lane layout within warp w:
//   l = 8*colblk + 2*g + uin   (colblk 0..3, gate g 0..3, uin 0..1)
//   unit  u   = 16r + 2w + uin
//   row       = g*128 + u            (in W, 4H x H)
//   columns   = [32*colblk, 32*colblk+32)
// Row sum: shfl_xor(8) + shfl_xor(16). Gate gather: 4 in-warp idx shuffles.
// ALL h propagation (including to self) is st.async + one mbarrier per step:
// no __syncthreads in the main loop.
__global__ void __launch_bounds__(256, 1) __cluster_dims__(CLS, 1, 1)
lstm_kernel(const float* __restrict__ x,
            const float* __restrict__ W_ih,
            const float* __restrict__ W_hh,
            const float* __restrict__ b_ih,
            const float* __restrict__ b_hh)
{
    __shared__ __align__(16) float h_sh[2][HID];   // double-buffered hidden state
    __shared__ __align__(8)  unsigned long long mbar[2];

    const int tid  = threadIdx.x;
    const int w    = tid >> 5;
    const int l    = tid & 31;
    const uint32_t rank = my_cluster_rank();
    const int chain = blockIdx.x / CLS;

    const int uin  = l & 1;                 // unit within warp's pair
    const int g    = (l >> 1) & 3;          // gate 0..3 (i,f,g,o)
    const int cb   = l >> 3;                // column block 0..3 (32 cols each)
    const int ug   = 16 * (int)rank + 2 * w + uin;  // global hidden unit
    const int row  = g * 128 + ug;          // row in W (4H x H)

    // Register-resident W_hh row chunk: 32 floats = 8 ull2 (16 regs)
    const ulonglong2* wrow =
        reinterpret_cast<const ulonglong2*>(W_hh + (size_t)row * HID + 32 * cb);
    ulonglong2 wv[8];
#pragma unroll
    for (int j = 0; j < 8; j++) wv[j] = wrow[j];

    const float wx0 = W_ih[row * 3 + 0];
    const float wx1 = W_ih[row * 3 + 1];
    const float wx2 = W_ih[row * 3 + 2];
    const float bsum = b_ih[row] + b_hh[row];

    if (tid < HID) h_sh[0][tid] = 0.f;

    const uint32_t mb_l0 = smem_u32(&mbar[0]);
    const uint32_t mb_l1 = smem_u32(&mbar[1]);
    if (tid == 0) {
        MBAR_INIT(mb_l0, 1);
        MBAR_INIT(mb_l1, 1);
        MBAR_EXPECT_TX(mb_l1, 512);   // step 0 fills buffer 1 (8 ranks x 16 x 4B)
    }
    __syncthreads();   // local h_sh[0] zeros + mbar init done
    CLUSTER_SYNC();    // mbar init visible cluster-wide before any st.async

    // st.async targets: one mapa base per rank (h_sh[0][ug]); buffer-1 slot and
    // both mbarriers derived by constant local-address deltas (same CTA window).
    const uint32_t la0 = smem_u32(&h_sh[0][ug]);
    const uint32_t d_h1  = smem_u32(&h_sh[1][ug]) - la0;
    const uint32_t d_mb0 = mb_l0 - la0;
    const uint32_t d_mb1 = mb_l1 - la0;
    uint32_t base[CLS];
#pragma unroll
    for (int k = 0; k < CLS; k++) base[k] = mapa_u32(la0, (uint32_t)k);

    float c = 0.f;        // cell state (lanes 0..1 of each warp)
    int ph0 = 0, ph1 = 0; // mbarrier phase parities

    // x layout: (B,N,F,T) -> element (s,f,t) at x[s*36 + f*12 + t]
    float x0 = x[chain], x1 = x[12 + chain], x2 = x[24 + chain];

#define LSTM_STEP(s, P)                                                        \
    {                                                                          \
        const int b = 1 - (P);                                                 \
        if (tid == 0 && (s) > 0 && (s) < S_STEPS - 1)                          \
            MBAR_EXPECT_TX((b) ? mb_l1 : mb_l0, 512);                          \
        /* prefetch next x (L2-resident, hidden under the wait) */             \
        float nx0 = 0.f, nx1 = 0.f, nx2 = 0.f;                                 \
        if ((s) + 1 < S_STEPS) {                                               \
            const float* xp = x + (size_t)((s) + 1) * 36 + chain;              \
            nx0 = __ldg(xp); nx1 = __ldg(xp + 12); nx2 = __ldg(xp + 24);       \
        }                                                                      \
        /* wait for all 128 h of step s (st.async from all 8 ranks) */         \
        if ((s) > 0) {                                                         \
            if (P) { MBAR_WAIT(mb_l1, ph1); ph1 ^= 1; }                        \
            else   { MBAR_WAIT(mb_l0, ph0); ph0 ^= 1; }                        \
        }                                                                      \
        /* 32-col chunk of one row: 16 fma2, 4 accumulator chains */           \
        const ulonglong2* h4 =                                                 \
            reinterpret_cast<const ulonglong2*>(&h_sh[P][32 * cb]);            \
        unsigned long long a0 = 0ull, a1 = 0ull, a2 = 0ull, a3 = 0ull;         \
        _Pragma("unroll")                                                      \
        for (int j = 0; j < 8; j += 2) {                                       \
            ulonglong2 hva = h4[j];                                            \
            a0 = fma2(wv[j].x, hva.x, a0);                                     \
            a1 = fma2(wv[j].y, hva.y, a1);                                     \
            ulonglong2 hvb = h4[j + 1];                                        \
            a2 = fma2(wv[j + 1].x, hvb.x, a2);                                 \
            a3 = fma2(wv[j + 1].y, hvb.y, a3);                                 \
        }                                                                      \
        float zs = (unpack_sum(a0) + unpack_sum(a1))                           \
                 + (unpack_sum(a2) + unpack_sum(a3));                          \
        const unsigned fm = 0xffffffffu;                                       \
        zs += __shfl_xor_sync(fm, zs, 8);                                      \
        zs += __shfl_xor_sync(fm, zs, 16);                                     \
        float z = zs + bsum + wx0 * x0 + wx1 * x1 + wx2 * x2;                  \
        /* gather 4 gates of my unit (lanes uin+2g, all in this warp) */       \
        float zi = __shfl_sync(fm, z, uin);                                    \
        float zf = __shfl_sync(fm, z, uin + 2);                                \
        float zg = __shfl_sync(fm, z, uin + 4);                                \
        float zo = __shfl_sync(fm, z, uin + 6);                                \
        if (l < 2) {                                                           \
            float si = sigmoid_fast(zi);                                       \
            float sf = sigmoid_fast(zf);                                       \
            float so = sigmoid_fast(zo);                                       \
            c = sf * c + si * tanh_fast(zg);                                   \
            float hv = so * tanh_fast(c);                                      \
            if ((s) + 1 < S_STEPS) {                                           \
                const uint32_t dh = (b) ? d_h1 : 0u;                           \
                const uint32_t dm = (b) ? d_mb1 : d_mb0;                       \
                _Pragma("unroll")                                              \
                for (int k = 0; k < CLS; k++)                                  \
                    st_async_f32(base[k] + dh, hv, base[k] + dm);              \
            }                                                                  \
            g_hhist[(size_t)((s) * NCH + chain) * HID + ug] = hv;              \
        }                                                                      \
        x0 = nx0; x1 = nx1; x2 = nx2;                                          \
    }

    for (int s = 0; s < S_STEPS; s += 2) {
        LSTM_STEP(s, 0);
        LSTM_STEP(s + 1, 1);
    }
#undef LSTM_STEP
}

// Deferred output projection: out[row] = b_lin + h_hist[row,:] . W_lin
__global__ void __launch_bounds__(256) out_kernel(
    const float* __restrict__ Wlin, const float* __restrict__ blin,
    float* __restrict__ out)
{
    const int lane = threadIdx.x & 31;
    const int warp = (blockIdx.x * blockDim.x + threadIdx.x) >> 5;
    const float w0 = Wlin[lane],      w1 = Wlin[lane + 32];
    const float w2 = Wlin[lane + 64], w3 = Wlin[lane + 96];
    const float bl = __ldg(blin);
    int row = warp * 8;
#pragma unroll
    for (int k = 0; k < 8; k++, row++) {
        if (row >= NROWS_TOTAL) return;
        const float* h = g_hhist + (size_t)row * HID;
        float s = h[lane] * w0 + h[lane + 32] * w1
                + h[lane + 64] * w2 + h[lane + 96] * w3;
#pragma unroll
        for (int off = 16; off; off >>= 1)
            s += __shfl_xor_sync(0xffffffffu, s, off);
        if (lane == 0) out[row] = s + bl;
    }
}

extern "C" void kernel_launch(void* const* d_in, const int* in_sizes, int n_in,
                              void* d_out, int out_size)
{
    const float* x     = (const float*)d_in[0];
    const float* W_ih  = (const float*)d_in[1];
    const float* W_hh  = (const float*)d_in[2];
    const float* b_ih  = (const float*)d_in[3];
    const float* b_hh  = (const float*)d_in[4];
    const float* W_lin = (const float*)d_in[5];
    const float* b_lin = (const float*)d_in[6];
    float* out = (float*)d_out;

    lstm_kernel<<<12 * CLS, 256>>>(x, W_ih, W_hh, b_ih, b_hh);
    out_kernel<<<3684, 256>>>(W_lin, b_lin, out);
}